// round 15
// baseline (speedup 1.0000x reference)
#include <cuda_runtime.h>
#include <cuda_bf16.h>
#include <cstdint>

// KAN layer as tensor-core GEMM (generic mma.sync path; tcgen05 blocked by
// harness compiling PTX at .target sm_103 without the 'a' suffix).
//   out[1024,128] = A[1024,1024] @ B^T + bias
//   A[n, j*8+k] = Catmull-Rom basis (built per tile, bf16 hi/lo split)
//   B[o, j*8+k] = weights[o,j]*coeffs[o,j,k]  (built IN-KERNEL per chunk, bf16 hi/lo)
// 3-pass bf16 mma (hh + hl + lh), fp32 accumulators ~ fp32 accuracy.
//
// SINGLE kernel: grid (16 m-tiles x 8 k-chunks) = 128 blocks, 256 threads.
//   8 warps = 4 m16-slices x 2 n64-halves. Warp tile: m16 x n64 x k128.
//   Partials -> g_part[kc][m][o]; the LAST block per m-tile (atomic counter)
//   reduces the 8 partials in fixed order + bias -> out. Deterministic, no
//   second launch, partials stay L2-hot.

#define D_IN  128
#define D_OUT 128
#define KNOTS 8
#define N_ROWS 1024
#define JK 1024
#define NKC 8
#define KCHUNK 128
#define MT 64                 // m rows per block

#define RSB 272               // SMEM row stride in bytes (136 bf16)
#define SM_AHI 0
#define SM_ALO (SM_AHI + MT * RSB)        // 17408
#define SM_BHI (SM_ALO + MT * RSB)        // 34816
#define SM_BLO (SM_BHI + D_OUT * RSB)     // 69632
#define SM_TOTAL (SM_BLO + D_OUT * RSB)   // 104448

__device__ float g_part[NKC * N_ROWS * D_OUT];  // 4 MB scratch
__device__ unsigned g_cnt[N_ROWS / MT];         // zero-init; reset after use

__device__ __forceinline__ uint32_t smem_u32(const void* p) {
    uint32_t a;
    asm("{ .reg .u64 t; cvta.to.shared.u64 t, %1; cvt.u32.u64 %0, t; }" : "=r"(a) : "l"(p));
    return a;
}

#define LDSM4(r0, r1, r2, r3, addr) \
    asm volatile("ldmatrix.sync.aligned.m8n8.x4.shared.b16 {%0,%1,%2,%3}, [%4];" \
        : "=r"(r0), "=r"(r1), "=r"(r2), "=r"(r3) : "r"(addr))

#define MMA16816(c, a0, a1, a2, a3, b0, b1) \
    asm volatile("mma.sync.aligned.m16n8k16.row.col.f32.bf16.bf16.f32 " \
        "{%0,%1,%2,%3}, {%4,%5,%6,%7}, {%8,%9}, {%0,%1,%2,%3};" \
        : "+f"((c)[0]), "+f"((c)[1]), "+f"((c)[2]), "+f"((c)[3]) \
        : "r"(a0), "r"(a1), "r"(a2), "r"(a3), "r"(b0), "r"(b1))

__global__ __launch_bounds__(256, 1) void kan_mma_kernel(
    const float* __restrict__ x,
    const float* __restrict__ coeffs,
    const float* __restrict__ weights,
    const float* __restrict__ bias,
    float* __restrict__ out) {
    extern __shared__ __align__(16) char smem[];
    const uint32_t sb = smem_u32(smem);
    const int tid  = threadIdx.x;
    const int wid  = tid >> 5;
    const int lane = tid & 31;
    const int wm   = wid & 3;        // m16 slice
    const int wn   = wid >> 2;       // n64 half
    const int mt   = blockIdx.x;     // m-tile (64 rows)
    const int kc   = blockIdx.y;     // k-chunk (128 k)

    // ---- Stage 1a: build A tile (64 rows x 16 j = 128 k), bf16 hi/lo ----
    #pragma unroll
    for (int e = tid; e < MT * 16; e += 256) {
        int m  = e >> 4;
        int jl = e & 15;
        int j  = kc * 16 + jl;
        float xv = x[(mt * MT + m) * D_IN + j];
        float xc = fminf(fmaxf(xv, -1.0f), 1.0f);
        float t  = (xc + 1.0f) * 3.5f;               // h = 2/7
        int idx  = min((int)floorf(t), 6);
        float u  = t - (float)idx;
        float u2 = u * u, u3 = u2 * u;
        float c0 = 0.5f * (-u3 + 2.0f * u2 - u);
        float c1 = 0.5f * (3.0f * u3 - 5.0f * u2 + 2.0f);
        float c2 = 0.5f * (-3.0f * u3 + 4.0f * u2 + u);
        float c3 = 0.5f * (u3 - u2);
        int p0 = max(idx - 1, 0);
        int p3 = min(idx + 2, 7);
        float v[8];
        #pragma unroll
        for (int k = 0; k < 8; k++) {
            float s = 0.0f;
            s += (k == p0)      ? c0 : 0.0f;
            s += (k == idx)     ? c1 : 0.0f;
            s += (k == idx + 1) ? c2 : 0.0f;
            s += (k == p3)      ? c3 : 0.0f;
            v[k] = s;
        }
        __nv_bfloat162 hi[4], lo[4];
        #pragma unroll
        for (int p = 0; p < 4; p++) {
            __nv_bfloat16 h0 = __float2bfloat16(v[2 * p]);
            __nv_bfloat16 h1 = __float2bfloat16(v[2 * p + 1]);
            hi[p] = __nv_bfloat162(h0, h1);
            lo[p] = __nv_bfloat162(
                __float2bfloat16(v[2 * p]     - __bfloat162float(h0)),
                __float2bfloat16(v[2 * p + 1] - __bfloat162float(h1)));
        }
        int off = m * RSB + jl * 16;
        *(uint4*)(smem + SM_AHI + off) = *(uint4*)hi;
        *(uint4*)(smem + SM_ALO + off) = *(uint4*)lo;
    }

    // ---- Stage 1b: build B chunk in-kernel (128 o x 16 j = 128 k), hi/lo ----
    #pragma unroll
    for (int e = tid; e < D_OUT * 16; e += 256) {
        int o  = e >> 4;
        int jl = e & 15;
        int j  = kc * 16 + jl;
        int oj = o * D_IN + j;
        float w = weights[oj];
        float4 cA = *(const float4*)&coeffs[oj * KNOTS];
        float4 cB = *(const float4*)&coeffs[oj * KNOTS + 4];
        float v[8] = { w * cA.x, w * cA.y, w * cA.z, w * cA.w,
                       w * cB.x, w * cB.y, w * cB.z, w * cB.w };
        __nv_bfloat162 hi[4], lo[4];
        #pragma unroll
        for (int p = 0; p < 4; p++) {
            __nv_bfloat16 h0 = __float2bfloat16(v[2 * p]);
            __nv_bfloat16 h1 = __float2bfloat16(v[2 * p + 1]);
            hi[p] = __nv_bfloat162(h0, h1);
            lo[p] = __nv_bfloat162(
                __float2bfloat16(v[2 * p]     - __bfloat162float(h0)),
                __float2bfloat16(v[2 * p + 1] - __bfloat162float(h1)));
        }
        int soff = o * RSB + jl * 16;
        *(uint4*)(smem + SM_BHI + soff) = *(uint4*)hi;
        *(uint4*)(smem + SM_BLO + soff) = *(uint4*)lo;
    }
    __syncthreads();

    // ---- Stage 2: mainloop, 8 k16 blocks x 4 n16 groups x 3 passes ----
    const uint32_t a_lane = (uint32_t)((wm * 16 + (lane & 7) + ((lane >> 3) & 1) * 8) * RSB
                                       + (lane >> 4) * 16);
    const uint32_t b_lane = (uint32_t)(((lane & 7) + (lane >> 4) * 8) * RSB
                                       + ((lane >> 3) & 1) * 16);
    const uint32_t aHI = sb + SM_AHI + a_lane;
    const uint32_t aLO = sb + SM_ALO + a_lane;
    const uint32_t bHI = sb + SM_BHI + b_lane + (uint32_t)(wn * 64 * RSB);
    const uint32_t bLO = sb + SM_BLO + b_lane + (uint32_t)(wn * 64 * RSB);

    float acc[8][4];
    #pragma unroll
    for (int nb = 0; nb < 8; nb++)
        #pragma unroll
        for (int q = 0; q < 4; q++) acc[nb][q] = 0.0f;

    #pragma unroll 1
    for (int kb = 0; kb < 8; kb++) {
        uint32_t koff = (uint32_t)(kb * 32);         // 16 k * 2B
        uint32_t ah0, ah1, ah2, ah3, al0, al1, al2, al3;
        LDSM4(ah0, ah1, ah2, ah3, aHI + koff);
        LDSM4(al0, al1, al2, al3, aLO + koff);

        #pragma unroll
        for (int ng = 0; ng < 4; ng++) {             // n16 group
            uint32_t noff = (uint32_t)(ng * 16 * RSB) + koff;
            uint32_t bh0, bh1, bh2, bh3, bl0, bl1, bl2, bl3;
            LDSM4(bh0, bh1, bh2, bh3, bHI + noff);
            LDSM4(bl0, bl1, bl2, bl3, bLO + noff);

            MMA16816(acc[2 * ng],     ah0, ah1, ah2, ah3, bh0, bh1);
            MMA16816(acc[2 * ng],     ah0, ah1, ah2, ah3, bl0, bl1);
            MMA16816(acc[2 * ng],     al0, al1, al2, al3, bh0, bh1);
            MMA16816(acc[2 * ng + 1], ah0, ah1, ah2, ah3, bh2, bh3);
            MMA16816(acc[2 * ng + 1], ah0, ah1, ah2, ah3, bl2, bl3);
            MMA16816(acc[2 * ng + 1], al0, al1, al2, al3, bh2, bh3);
        }
    }

    // ---- Stage 3: write partials ----
    {
        const int gid = lane >> 2;
        const int tig = lane & 3;
        const int row0 = mt * MT + wm * 16 + gid;
        float* base = &g_part[(size_t)kc * (N_ROWS * D_OUT)];
        #pragma unroll
        for (int nb = 0; nb < 8; nb++) {
            int col = wn * 64 + nb * 8 + tig * 2;
            *(float2*)&base[(size_t)row0 * D_OUT + col]       = make_float2(acc[nb][0], acc[nb][1]);
            *(float2*)&base[(size_t)(row0 + 8) * D_OUT + col] = make_float2(acc[nb][2], acc[nb][3]);
        }
    }

    // ---- Stage 4: last block per m-tile reduces 8 partials + bias -> out ----
    __threadfence();                                 // partials visible grid-wide
    __shared__ unsigned s_last;
    if (tid == 0) s_last = atomicAdd(&g_cnt[mt], 1);
    __syncthreads();
    if (s_last == NKC - 1) {
        // 64 rows x 32 float4-cols = 2048 tasks, 8 per thread; fixed sum order.
        #pragma unroll
        for (int e = tid; e < MT * (D_OUT / 4); e += 256) {
            int r  = e >> 5;                         // 0..63
            int c4 = (e & 31) * 4;
            int m  = mt * MT + r;
            float4 s = *(const float4*)&g_part[(size_t)m * D_OUT + c4];
            #pragma unroll
            for (int kq = 1; kq < NKC; kq++) {
                float4 p = *(const float4*)&g_part[((size_t)kq * N_ROWS + m) * D_OUT + c4];
                s.x += p.x; s.y += p.y; s.z += p.z; s.w += p.w;
            }
            float4 bv = *(const float4*)&bias[c4];
            s.x += bv.x; s.y += bv.y; s.z += bv.z; s.w += bv.w;
            *(float4*)&out[(size_t)m * D_OUT + c4] = s;
        }
        __syncthreads();
        if (tid == 0) g_cnt[mt] = 0;                 // reset for next graph replay
    }
}

extern "C" void kernel_launch(void* const* d_in, const int* in_sizes, int n_in,
                              void* d_out, int out_size) {
    const float* x       = (const float*)d_in[0];   // [1024,128]
    const float* coeffs  = (const float*)d_in[1];   // [128,128,8]
    const float* weights = (const float*)d_in[2];   // [128,128]
    const float* bias    = (const float*)d_in[3];   // [128]
    float* out = (float*)d_out;                     // [1024,128]

    cudaFuncSetAttribute(kan_mma_kernel,
                         cudaFuncAttributeMaxDynamicSharedMemorySize, SM_TOTAL);

    dim3 grid(N_ROWS / MT, NKC);                    // (16, 8)
    kan_mma_kernel<<<grid, 256, SM_TOTAL>>>(x, coeffs, weights, bias, out);
}

// round 16
// speedup vs baseline: 1.2480x; 1.2480x over previous
#include <cuda_runtime.h>
#include <cuda_bf16.h>
#include <cstdint>

// KAN layer as tensor-core GEMM (generic mma.sync path).
//   out[1024,128] = A[1024,1024] @ B^T + bias
//   A[n, j*8+k] = Catmull-Rom basis (built per tile, bf16 hi/lo split)
//   B[o, j*8+k] = weights[o,j]*coeffs[o,j,k]  (built in-kernel per chunk, bf16 hi/lo)
// 3-pass bf16 mma (hh + hl + lh), fp32 accumulators ~ fp32 accuracy.
//
// Main kernel: grid (16 mt x 2 oh x 4 kc) = 128 blocks, 256 threads.
//   Block tile: 64 m x 64 o x 256 k. 8 warps = 4 m16-slices x 2 n32-slices.
//   Warp tile: m16 x n32 x k256 (16 kb-steps, 12 MMA each = 192 total).
//   Partials -> g_part[kc][m][o] (2 MB, NKC=4).
// Reduce kernel: 4 explicit loads (MLP=4) + fixed-order tree sum + bias.

#define D_IN  128
#define D_OUT 128
#define KNOTS 8
#define N_ROWS 1024
#define NKC 4
#define KCJ 32                // j per chunk (= 256 k)
#define MT 64                 // m rows per block
#define OB 64                 // o per block

#define RSB 528               // SMEM row stride bytes (256 bf16 = 512 + 16 pad)
#define SM_AHI 0
#define SM_ALO (SM_AHI + MT * RSB)        // 33792
#define SM_BHI (SM_ALO + MT * RSB)        // 67584
#define SM_BLO (SM_BHI + OB * RSB)        // 101376
#define SM_TOTAL (SM_BLO + OB * RSB)      // 135168

__device__ float g_part[NKC * N_ROWS * D_OUT];  // 2 MB scratch

__device__ __forceinline__ uint32_t smem_u32(const void* p) {
    uint32_t a;
    asm("{ .reg .u64 t; cvta.to.shared.u64 t, %1; cvt.u32.u64 %0, t; }" : "=r"(a) : "l"(p));
    return a;
}

#define LDSM4(r0, r1, r2, r3, addr) \
    asm volatile("ldmatrix.sync.aligned.m8n8.x4.shared.b16 {%0,%1,%2,%3}, [%4];" \
        : "=r"(r0), "=r"(r1), "=r"(r2), "=r"(r3) : "r"(addr))

#define MMA16816(c, a0, a1, a2, a3, b0, b1) \
    asm volatile("mma.sync.aligned.m16n8k16.row.col.f32.bf16.bf16.f32 " \
        "{%0,%1,%2,%3}, {%4,%5,%6,%7}, {%8,%9}, {%0,%1,%2,%3};" \
        : "+f"((c)[0]), "+f"((c)[1]), "+f"((c)[2]), "+f"((c)[3]) \
        : "r"(a0), "r"(a1), "r"(a2), "r"(a3), "r"(b0), "r"(b1))

__global__ __launch_bounds__(256, 1) void kan_mma_kernel(
    const float* __restrict__ x,
    const float* __restrict__ coeffs,
    const float* __restrict__ weights) {
    extern __shared__ __align__(16) char smem[];
    const uint32_t sb = smem_u32(smem);
    const int tid  = threadIdx.x;
    const int wid  = tid >> 5;
    const int lane = tid & 31;
    const int wm   = wid & 3;        // m16 slice
    const int wn   = wid >> 2;       // n32 slice (0/1)
    const int mt   = blockIdx.x;     // m-tile (64 rows)
    const int oh   = blockIdx.y;     // o-half (64 cols)
    const int kc   = blockIdx.z;     // k-chunk (256 k = 32 j)

    // ---- Stage 1a: build A tile (64 m x 32 j = 256 k), bf16 hi/lo ----
    #pragma unroll
    for (int e = tid; e < MT * KCJ; e += 256) {
        int m  = e >> 5;
        int jl = e & 31;
        int j  = kc * KCJ + jl;
        float xv = x[(mt * MT + m) * D_IN + j];
        float xc = fminf(fmaxf(xv, -1.0f), 1.0f);
        float t  = (xc + 1.0f) * 3.5f;               // h = 2/7
        int idx  = min((int)floorf(t), 6);
        float u  = t - (float)idx;
        float u2 = u * u, u3 = u2 * u;
        float c0 = 0.5f * (-u3 + 2.0f * u2 - u);
        float c1 = 0.5f * (3.0f * u3 - 5.0f * u2 + 2.0f);
        float c2 = 0.5f * (-3.0f * u3 + 4.0f * u2 + u);
        float c3 = 0.5f * (u3 - u2);
        int p0 = max(idx - 1, 0);
        int p3 = min(idx + 2, 7);
        float v[8];
        #pragma unroll
        for (int k = 0; k < 8; k++) {
            float s = 0.0f;
            s += (k == p0)      ? c0 : 0.0f;
            s += (k == idx)     ? c1 : 0.0f;
            s += (k == idx + 1) ? c2 : 0.0f;
            s += (k == p3)      ? c3 : 0.0f;
            v[k] = s;
        }
        __nv_bfloat162 hi[4], lo[4];
        #pragma unroll
        for (int p = 0; p < 4; p++) {
            __nv_bfloat16 h0 = __float2bfloat16(v[2 * p]);
            __nv_bfloat16 h1 = __float2bfloat16(v[2 * p + 1]);
            hi[p] = __nv_bfloat162(h0, h1);
            lo[p] = __nv_bfloat162(
                __float2bfloat16(v[2 * p]     - __bfloat162float(h0)),
                __float2bfloat16(v[2 * p + 1] - __bfloat162float(h1)));
        }
        int off = m * RSB + jl * 16;
        *(uint4*)(smem + SM_AHI + off) = *(uint4*)hi;
        *(uint4*)(smem + SM_ALO + off) = *(uint4*)lo;
    }

    // ---- Stage 1b: build B chunk (64 o x 32 j = 256 k), bf16 hi/lo ----
    #pragma unroll
    for (int e = tid; e < OB * KCJ; e += 256) {
        int ol = e >> 5;
        int jl = e & 31;
        int o  = oh * OB + ol;
        int j  = kc * KCJ + jl;
        int oj = o * D_IN + j;
        float w = weights[oj];
        float4 cA = *(const float4*)&coeffs[oj * KNOTS];
        float4 cB = *(const float4*)&coeffs[oj * KNOTS + 4];
        float v[8] = { w * cA.x, w * cA.y, w * cA.z, w * cA.w,
                       w * cB.x, w * cB.y, w * cB.z, w * cB.w };
        __nv_bfloat162 hi[4], lo[4];
        #pragma unroll
        for (int p = 0; p < 4; p++) {
            __nv_bfloat16 h0 = __float2bfloat16(v[2 * p]);
            __nv_bfloat16 h1 = __float2bfloat16(v[2 * p + 1]);
            hi[p] = __nv_bfloat162(h0, h1);
            lo[p] = __nv_bfloat162(
                __float2bfloat16(v[2 * p]     - __bfloat162float(h0)),
                __float2bfloat16(v[2 * p + 1] - __bfloat162float(h1)));
        }
        int soff = ol * RSB + jl * 16;
        *(uint4*)(smem + SM_BHI + soff) = *(uint4*)hi;
        *(uint4*)(smem + SM_BLO + soff) = *(uint4*)lo;
    }
    __syncthreads();

    // ---- Stage 2: mainloop, 16 kb-steps x 2 n16 groups x 3 passes ----
    // A frag: row = wm*16 + (L&7) + ((L>>3)&1)*8, col16 = L>>4
    // B frag: row = n0 + (L&7) + (L>>4)*8,        col16 = (L>>3)&1
    const uint32_t a_lane = (uint32_t)((wm * 16 + (lane & 7) + ((lane >> 3) & 1) * 8) * RSB
                                       + (lane >> 4) * 16);
    const uint32_t b_lane = (uint32_t)(((lane & 7) + (lane >> 4) * 8) * RSB
                                       + ((lane >> 3) & 1) * 16);
    const uint32_t aHI = sb + SM_AHI + a_lane;
    const uint32_t aLO = sb + SM_ALO + a_lane;
    const uint32_t bHI = sb + SM_BHI + b_lane + (uint32_t)(wn * 32 * RSB);
    const uint32_t bLO = sb + SM_BLO + b_lane + (uint32_t)(wn * 32 * RSB);

    float acc[4][4];
    #pragma unroll
    for (int nb = 0; nb < 4; nb++)
        #pragma unroll
        for (int q = 0; q < 4; q++) acc[nb][q] = 0.0f;

    #pragma unroll 1
    for (int kb = 0; kb < 16; kb++) {
        uint32_t koff = (uint32_t)(kb * 32);         // 16 k * 2B
        uint32_t ah0, ah1, ah2, ah3, al0, al1, al2, al3;
        LDSM4(ah0, ah1, ah2, ah3, aHI + koff);
        LDSM4(al0, al1, al2, al3, aLO + koff);

        #pragma unroll
        for (int ng = 0; ng < 2; ng++) {             // n16 group
            uint32_t noff = (uint32_t)(ng * 16 * RSB) + koff;
            uint32_t bh0, bh1, bh2, bh3, bl0, bl1, bl2, bl3;
            LDSM4(bh0, bh1, bh2, bh3, bHI + noff);
            LDSM4(bl0, bl1, bl2, bl3, bLO + noff);

            MMA16816(acc[2 * ng],     ah0, ah1, ah2, ah3, bh0, bh1);
            MMA16816(acc[2 * ng],     ah0, ah1, ah2, ah3, bl0, bl1);
            MMA16816(acc[2 * ng],     al0, al1, al2, al3, bh0, bh1);
            MMA16816(acc[2 * ng + 1], ah0, ah1, ah2, ah3, bh2, bh3);
            MMA16816(acc[2 * ng + 1], ah0, ah1, ah2, ah3, bl2, bl3);
            MMA16816(acc[2 * ng + 1], al0, al1, al2, al3, bh2, bh3);
        }
    }

    // ---- Stage 3: write partials ----
    {
        const int gid = lane >> 2;
        const int tig = lane & 3;
        const int row0 = mt * MT + wm * 16 + gid;
        float* base = &g_part[(size_t)kc * (N_ROWS * D_OUT)];
        #pragma unroll
        for (int nb = 0; nb < 4; nb++) {
            int col = oh * OB + wn * 32 + nb * 8 + tig * 2;
            *(float2*)&base[(size_t)row0 * D_OUT + col]       = make_float2(acc[nb][0], acc[nb][1]);
            *(float2*)&base[(size_t)(row0 + 8) * D_OUT + col] = make_float2(acc[nb][2], acc[nb][3]);
        }
    }
}

// ---------- reduce: 4 explicit loads (MLP=4) + tree sum + bias ----------
__global__ void reduce_kernel(const float* __restrict__ bias, float* __restrict__ out) {
    int t = blockIdx.x * blockDim.x + threadIdx.x;   // 0 .. 32767
    int m  = t >> 5;
    int c4 = (t & 31) * 4;
    size_t off = (size_t)m * D_OUT + c4;
    const size_t S = (size_t)N_ROWS * D_OUT;
    float4 p0 = *(const float4*)&g_part[off];
    float4 p1 = *(const float4*)&g_part[S + off];
    float4 p2 = *(const float4*)&g_part[2 * S + off];
    float4 p3 = *(const float4*)&g_part[3 * S + off];
    float4 bv = *(const float4*)&bias[c4];
    float4 s;
    s.x = (p0.x + p1.x) + (p2.x + p3.x) + bv.x;
    s.y = (p0.y + p1.y) + (p2.y + p3.y) + bv.y;
    s.z = (p0.z + p1.z) + (p2.z + p3.z) + bv.z;
    s.w = (p0.w + p1.w) + (p2.w + p3.w) + bv.w;
    *(float4*)&out[off] = s;
}

extern "C" void kernel_launch(void* const* d_in, const int* in_sizes, int n_in,
                              void* d_out, int out_size) {
    const float* x       = (const float*)d_in[0];   // [1024,128]
    const float* coeffs  = (const float*)d_in[1];   // [128,128,8]
    const float* weights = (const float*)d_in[2];   // [128,128]
    const float* bias    = (const float*)d_in[3];   // [128]
    float* out = (float*)d_out;                     // [1024,128]

    cudaFuncSetAttribute(kan_mma_kernel,
                         cudaFuncAttributeMaxDynamicSharedMemorySize, SM_TOTAL);

    dim3 grid(N_ROWS / MT, D_OUT / OB, NKC);        // (16, 2, 4)
    kan_mma_kernel<<<grid, 256, SM_TOTAL>>>(x, coeffs, weights);
    reduce_kernel<<<(N_ROWS * D_OUT / 4) / 256, 256>>>(bias, out);
}